// round 10
// baseline (speedup 1.0000x reference)
#include <cuda_runtime.h>
#include <cuda_fp16.h>
#include <cuda_bf16.h>

#define N_NODES   50000
#define N_EDGES   1600000
#define HID       128
#define KTOT      256            // combined K = [agg | x]
#define N_LAYERS  3
#define N_GRAPHS  64
#define LN_EPS    1e-5f
#define SCAN_B    ((N_NODES + 255) / 256)   // 196
#define POOL_B    ((N_NODES + 127) / 128)   // 391
#define GT_ROWS   128

// ---------------- static device scratch ---------------------------------------
__device__ __half g_xA  [(size_t)N_NODES * HID];    // fp16 layer input (ping)
__device__ __half g_xB  [(size_t)N_NODES * HID];    // fp16 layer input (pong)
__device__ __half g_wh  [(size_t)N_LAYERS * HID * KTOT]; // [l][n][k], transposed
__device__ int    g_deg_i[N_NODES];
__device__ int    g_cur  [N_NODES];
__device__ int    g_incl [N_NODES];
__device__ int    g_part [256];
__device__ int    g_csr  [N_EDGES];
__device__ int    g_scan_done;
__device__ int    g_pool_done;
__device__ float  g_gsum[N_GRAPHS * HID];
__device__ float  g_gcnt[N_GRAPHS];

// ---------------- fused init: zero + fp16 convert + weight transpose ----------
__global__ void init_kernel(const float* __restrict__ x,
                            const float* __restrict__ Wn,
                            const float* __restrict__ Wr) {
    int i = blockIdx.x * blockDim.x + threadIdx.x;     // 0 .. 1.6M-1
    if (i < N_NODES) { g_deg_i[i] = 0; g_cur[i] = 0; }
    if (i < N_GRAPHS * HID) g_gsum[i] = 0.0f;
    if (i < N_GRAPHS) g_gcnt[i] = 0.0f;
    if (i == 0) { g_scan_done = 0; g_pool_done = 0; }
    size_t e = (size_t)i * 4;
    if (e < (size_t)N_NODES * HID) {
        float4 v = *(const float4*)(x + e);
        __half2 h0 = __floats2half2_rn(v.x, v.y);
        __half2 h1 = __floats2half2_rn(v.z, v.w);
        uint2 packed;
        packed.x = *(unsigned*)&h0;
        packed.y = *(unsigned*)&h1;
        *(uint2*)(g_xA + e) = packed;
    }
    if (i < N_LAYERS * HID * KTOT) {
        int k = i & 255;
        int n = (i >> 8) & 127;
        int l = i >> 15;
        float v = (k < HID) ? __ldg(&Wn[((size_t)l * HID + k) * HID + n])
                            : __ldg(&Wr[((size_t)l * HID + (k - HID)) * HID + n]);
        g_wh[i] = __float2half_rn(v);
    }
}

// ---------------- CSR build (R8-proven form) ----------------------------------
__global__ void count_kernel(const int* __restrict__ ei, int nE) {
    int e = blockIdx.x * blockDim.x + threadIdx.x;
    if (e >= nE) return;
    atomicAdd(&g_deg_i[__ldg(ei + nE + e)], 1);     // fire-and-forget -> RED
}

__global__ void scan12_kernel() {
    __shared__ int s[256];
    __shared__ int lastflag;
    int t = threadIdx.x;
    int i = blockIdx.x * 256 + t;
    int v = (i < N_NODES) ? g_deg_i[i] : 0;
    s[t] = v; __syncthreads();
    #pragma unroll
    for (int d = 1; d < 256; d <<= 1) {
        int u = (t >= d) ? s[t - d] : 0;
        __syncthreads();
        s[t] += u;
        __syncthreads();
    }
    if (i < N_NODES) g_incl[i] = s[t];
    if (t == 255) g_part[blockIdx.x] = s[255];
    __threadfence();
    if (t == 0) {
        int old = atomicAdd(&g_scan_done, 1);
        lastflag = (old == gridDim.x - 1);
    }
    __syncthreads();
    if (lastflag) {
        int pv = (t < SCAN_B) ? g_part[t] : 0;
        s[t] = pv; __syncthreads();
        #pragma unroll
        for (int d = 1; d < 256; d <<= 1) {
            int u = (t >= d) ? s[t - d] : 0;
            __syncthreads();
            s[t] += u;
            __syncthreads();
        }
        if (t < SCAN_B) g_part[t] = s[t] - pv;   // exclusive
    }
}

__global__ void fill_kernel(const int* __restrict__ ei, int nE) {
    int e = blockIdx.x * blockDim.x + threadIdx.x;
    if (e >= nE) return;
    int s = __ldg(ei + e);
    int d = __ldg(ei + nE + e);
    int base = __ldg(&g_part[d >> 8]) + __ldg(&g_incl[d]) - __ldg(&g_deg_i[d]);
    int pos = base + atomicAdd(&g_cur[d], 1);
    g_csr[pos] = s;
}

// ---------------- fused gather + HMMA dual-GEMM + LN + ReLU -------------------
// Phase A: 8 warps x 16 nodes each -> mean-neighbor sums written fp16 directly
//          into swizzled A_s (cols 0-127) + x row copy (cols 128-255).
// Phase B: weights; MMA; LN; ReLU; write next-layer fp16 (or fp32 out).
__device__ __forceinline__ unsigned ldsm_addr(const __half* base_sm, int row, int chunk) {
    return (unsigned)__cvta_generic_to_shared(base_sm) +
           (((row << 5) + (chunk ^ (row & 7))) << 4);
}

__global__ __launch_bounds__(256, 1) void fused_layer_kernel(
    const __half* __restrict__ x_cur, __half* __restrict__ x_next,
    const float* __restrict__ bn, const float* __restrict__ gamma,
    const float* __restrict__ beta, float* __restrict__ out_fp32,
    int layer, int write_fp32)
{
    extern __shared__ __half smh[];
    __half* A_s = smh;                  // 128*256 swizzled
    __half* W_s = smh + GT_ROWS * KTOT; // 128*256 swizzled
    float*  red = (float*)smh;          // epilogue reuse

    const int tid  = threadIdx.x;
    const int lane = tid & 31;
    const int warp = tid >> 5;
    const int row0 = blockIdx.x * GT_ROWS;

    // ---- Phase A: gather 16 nodes per warp + x copy ----
    {
        const int c_agg = lane >> 1;            // 16B chunk 0..15
        const int c_x   = 16 + (lane >> 1);     // 16B chunk 16..31
        const int half_off = (lane & 1) * 4;    // halves within chunk
        for (int t = 0; t < 16; t++) {
            int r   = warp * 16 + t;
            int row = row0 + r;
            float a0 = 0.f, a1 = 0.f, a2 = 0.f, a3 = 0.f;
            uint2 xv = make_uint2(0, 0);
            uint2 av = make_uint2(0, 0);
            if (row < N_NODES) {
                int deg = __ldg(&g_deg_i[row]);
                int beg = __ldg(&g_part[row >> 8]) + __ldg(&g_incl[row]) - deg;
                int j = 0;
                for (; j + 4 <= deg; j += 4) {
                    int i0 = __ldg(&g_csr[beg + j]);
                    int i1 = __ldg(&g_csr[beg + j + 1]);
                    int i2 = __ldg(&g_csr[beg + j + 2]);
                    int i3 = __ldg(&g_csr[beg + j + 3]);
                    uint2 v0 = __ldg((const uint2*)(x_cur + (size_t)i0 * HID) + lane);
                    uint2 v1 = __ldg((const uint2*)(x_cur + (size_t)i1 * HID) + lane);
                    uint2 v2 = __ldg((const uint2*)(x_cur + (size_t)i2 * HID) + lane);
                    uint2 v3 = __ldg((const uint2*)(x_cur + (size_t)i3 * HID) + lane);
                    float2 f;
                    f = __half22float2(*(__half2*)&v0.x); a0 += f.x; a1 += f.y;
                    f = __half22float2(*(__half2*)&v0.y); a2 += f.x; a3 += f.y;
                    f = __half22float2(*(__half2*)&v1.x); a0 += f.x; a1 += f.y;
                    f = __half22float2(*(__half2*)&v1.y); a2 += f.x; a3 += f.y;
                    f = __half22float2(*(__half2*)&v2.x); a0 += f.x; a1 += f.y;
                    f = __half22float2(*(__half2*)&v2.y); a2 += f.x; a3 += f.y;
                    f = __half22float2(*(__half2*)&v3.x); a0 += f.x; a1 += f.y;
                    f = __half22float2(*(__half2*)&v3.y); a2 += f.x; a3 += f.y;
                }
                for (; j < deg; j++) {
                    int i0 = __ldg(&g_csr[beg + j]);
                    uint2 v0 = __ldg((const uint2*)(x_cur + (size_t)i0 * HID) + lane);
                    float2 f;
                    f = __half22float2(*(__half2*)&v0.x); a0 += f.x; a1 += f.y;
                    f = __half22float2(*(__half2*)&v0.y); a2 += f.x; a3 += f.y;
                }
                float id = 1.0f / fmaxf((float)deg, 1.0f);
                __half2 h0 = __floats2half2_rn(a0 * id, a1 * id);
                __half2 h1 = __floats2half2_rn(a2 * id, a3 * id);
                av.x = *(unsigned*)&h0;
                av.y = *(unsigned*)&h1;
                xv = __ldg((const uint2*)(x_cur + (size_t)row * HID) + lane);
            }
            *(uint2*)(A_s + (((r << 5) + (c_agg ^ (r & 7))) << 3) + half_off) = av;
            *(uint2*)(A_s + (((r << 5) + (c_x   ^ (r & 7))) << 3) + half_off) = xv;
        }
    }

    // ---- Phase B: stage weights ----
    const __half* wl = g_wh + (size_t)layer * HID * KTOT;
    for (int q = tid; q < HID * 32; q += 256) {
        int n = q >> 5;
        int c = q & 31;
        uint4 v = *(const uint4*)(wl + (size_t)n * KTOT + c * 8);
        *(uint4*)(W_s + (((n << 5) + (c ^ (n & 7))) << 3)) = v;
    }
    __syncthreads();

    // ---- MMA mainloop ----
    const int wm = warp & 3;
    const int wn = warp >> 2;
    const int m0 = wm * 32;
    const int n0 = wn * 64;

    float acc[2][8][4];
    #pragma unroll
    for (int mt = 0; mt < 2; mt++)
        #pragma unroll
        for (int nt = 0; nt < 8; nt++)
            #pragma unroll
            for (int v = 0; v < 4; v++) acc[mt][nt][v] = 0.0f;

    const int a_row0 = m0 + (lane & 15);
    const int b_row0 = n0 + (lane & 15);
    const int hi     = lane >> 4;

    #pragma unroll 4
    for (int kk = 0; kk < KTOT / 16; kk++) {
        int cbase = kk * 2 + hi;
        unsigned a[2][4];
        #pragma unroll
        for (int mt = 0; mt < 2; mt++) {
            unsigned addr = ldsm_addr(A_s, a_row0 + mt * 16, cbase);
            asm volatile("ldmatrix.sync.aligned.m8n8.x4.shared.b16 {%0,%1,%2,%3}, [%4];"
                         : "=r"(a[mt][0]), "=r"(a[mt][1]), "=r"(a[mt][2]), "=r"(a[mt][3])
                         : "r"(addr));
        }
        unsigned b[8][2];
        #pragma unroll
        for (int g = 0; g < 4; g++) {
            unsigned r0, r1, r2, r3;
            unsigned addr = ldsm_addr(W_s, b_row0 + g * 16, cbase);
            asm volatile("ldmatrix.sync.aligned.m8n8.x4.shared.b16 {%0,%1,%2,%3}, [%4];"
                         : "=r"(r0), "=r"(r1), "=r"(r2), "=r"(r3) : "r"(addr));
            b[g * 2 + 0][0] = r0; b[g * 2 + 0][1] = r2;
            b[g * 2 + 1][0] = r1; b[g * 2 + 1][1] = r3;
        }
        #pragma unroll
        for (int mt = 0; mt < 2; mt++)
            #pragma unroll
            for (int nt = 0; nt < 8; nt++)
                asm volatile(
                    "mma.sync.aligned.m16n8k16.row.col.f32.f16.f16.f32 "
                    "{%0,%1,%2,%3}, {%4,%5,%6,%7}, {%8,%9}, {%0,%1,%2,%3};"
                    : "+f"(acc[mt][nt][0]), "+f"(acc[mt][nt][1]),
                      "+f"(acc[mt][nt][2]), "+f"(acc[mt][nt][3])
                    : "r"(a[mt][0]), "r"(a[mt][1]), "r"(a[mt][2]), "r"(a[mt][3]),
                      "r"(b[nt][0]), "r"(b[nt][1]));
    }

    // ---- epilogue: bias, LN stats, affine, relu ----
    const int gid  = lane >> 2;
    const int pair = lane & 3;

    float2 bv[8], gv[8], btv[8];
    #pragma unroll
    for (int nt = 0; nt < 8; nt++) {
        int col = n0 + nt * 8 + pair * 2;
        bv[nt]  = *(const float2*)(bn    + layer * HID + col);
        gv[nt]  = *(const float2*)(gamma + layer * HID + col);
        btv[nt] = *(const float2*)(beta  + layer * HID + col);
    }
    #pragma unroll
    for (int mt = 0; mt < 2; mt++)
        #pragma unroll
        for (int nt = 0; nt < 8; nt++) {
            acc[mt][nt][0] += bv[nt].x; acc[mt][nt][1] += bv[nt].y;
            acc[mt][nt][2] += bv[nt].x; acc[mt][nt][3] += bv[nt].y;
        }

    float s[4] = {0, 0, 0, 0}, qq[4] = {0, 0, 0, 0};
    #pragma unroll
    for (int mt = 0; mt < 2; mt++)
        #pragma unroll
        for (int nt = 0; nt < 8; nt++) {
            float c0 = acc[mt][nt][0], c1 = acc[mt][nt][1];
            float c2 = acc[mt][nt][2], c3 = acc[mt][nt][3];
            s [mt * 2 + 0] += c0 + c1;       qq[mt * 2 + 0] += c0 * c0 + c1 * c1;
            s [mt * 2 + 1] += c2 + c3;       qq[mt * 2 + 1] += c2 * c2 + c3 * c3;
        }
    #pragma unroll
    for (int v = 0; v < 4; v++) {
        s [v] += __shfl_xor_sync(0xffffffffu, s [v], 1);
        s [v] += __shfl_xor_sync(0xffffffffu, s [v], 2);
        qq[v] += __shfl_xor_sync(0xffffffffu, qq[v], 1);
        qq[v] += __shfl_xor_sync(0xffffffffu, qq[v], 2);
    }

    __syncthreads();
    if (pair == 0) {
        #pragma unroll
        for (int v = 0; v < 4; v++) {
            int rl = m0 + (v >> 1) * 16 + (v & 1) * 8 + gid;
            red[wn * 128 + rl]       = s[v];
            red[256 + wn * 128 + rl] = qq[v];
        }
    }
    __syncthreads();

    const float inv128 = 1.0f / 128.0f;
    #pragma unroll
    for (int v = 0; v < 4; v++) {
        int rl  = m0 + (v >> 1) * 16 + (v & 1) * 8 + gid;
        int row = row0 + rl;
        float ts = red[rl] + red[128 + rl];
        float tq = red[256 + rl] + red[384 + rl];
        float mu  = ts * inv128;
        float var = tq * inv128 - mu * mu;
        float rs  = rsqrtf(var + LN_EPS);
        if (row < N_NODES) {
            int mt = v >> 1;
            int lo = (v & 1) * 2;
            #pragma unroll
            for (int nt = 0; nt < 8; nt++) {
                float o0 = fmaxf((acc[mt][nt][lo + 0] - mu) * rs * gv[nt].x + btv[nt].x, 0.0f);
                float o1 = fmaxf((acc[mt][nt][lo + 1] - mu) * rs * gv[nt].y + btv[nt].y, 0.0f);
                int col = n0 + nt * 8 + pair * 2;
                if (write_fp32) {
                    *(float2*)(out_fp32 + (size_t)row * HID + col) = make_float2(o0, o1);
                } else {
                    __half2 h = __floats2half2_rn(o0, o1);
                    *(__half2*)(x_next + (size_t)row * HID + col) = h;
                }
            }
        }
    }
}

// ---------------- graph pooling + finalize (fused via done-counter) -----------
__global__ __launch_bounds__(128) void pool_kernel(
    const float* __restrict__ node_emb, const int* __restrict__ batch,
    float* __restrict__ out_graph)
{
    __shared__ int sb[128];
    __shared__ int lastflag;
    int n0 = blockIdx.x * 128;
    int c  = threadIdx.x;
    int nmax = min(128, N_NODES - n0);
    if (c < nmax) sb[c] = batch[n0 + c];
    __syncthreads();

    float sum = 0.f;
    int curg = sb[0];
    int runlen = 0;
    for (int t = 0; t < nmax; t++) {
        int g = sb[t];
        if (g != curg) {
            atomicAdd(&g_gsum[curg * HID + c], sum);
            if (c == 0) atomicAdd(&g_gcnt[curg], (float)runlen);
            sum = 0.f; runlen = 0; curg = g;
        }
        sum += node_emb[(size_t)(n0 + t) * HID + c];
        runlen++;
    }
    atomicAdd(&g_gsum[curg * HID + c], sum);
    if (c == 0) atomicAdd(&g_gcnt[curg], (float)runlen);

    __threadfence();
    if (c == 0) {
        int old = atomicAdd(&g_pool_done, 1);
        lastflag = (old == gridDim.x - 1);
    }
    __syncthreads();
    if (lastflag) {
        for (int i = c; i < N_GRAPHS * HID; i += 128) {
            int g = i >> 7;
            float cnt = fmaxf(g_gcnt[g], 1.0f);
            out_graph[i] = g_gsum[i] / cnt;
        }
    }
}

extern "C" void kernel_launch(void* const* d_in, const int* in_sizes, int n_in,
                              void* d_out, int out_size)
{
    const float* x     = (const float*)d_in[0];
    const float* Wn    = (const float*)d_in[1];
    const float* bn    = (const float*)d_in[2];
    const float* Wr    = (const float*)d_in[3];
    const float* gamma = (const float*)d_in[4];
    const float* beta  = (const float*)d_in[5];
    const int*   ei    = (const int*)  d_in[6];
    const int*   batch = (const int*)  d_in[7];
    float* out = (float*)d_out;
    float* out_graph = out;                       // [64,128]
    float* out_node  = out + N_GRAPHS * HID;      // [50000,128]

    const int nE = in_sizes[6] / 2;

    static __half *pA = nullptr, *pB = nullptr;
    if (!pA) {
        cudaGetSymbolAddress((void**)&pA, g_xA);
        cudaGetSymbolAddress((void**)&pB, g_xB);
        cudaFuncSetAttribute(fused_layer_kernel,
                             cudaFuncAttributeMaxDynamicSharedMemorySize,
                             2 * GT_ROWS * KTOT * (int)sizeof(__half));
    }
    const size_t smem = 2 * GT_ROWS * KTOT * sizeof(__half);   // 128 KB

    // fused init: zero + fp16 convert + weight transpose
    init_kernel<<<((N_NODES * HID / 4) + 255) / 256, 256>>>(x, Wn, Wr);
    // CSR build (R8-proven: RED count + cursor fill)
    count_kernel<<<(nE + 255) / 256, 256>>>(ei, nE);
    scan12_kernel<<<SCAN_B, 256>>>();
    fill_kernel<<<(nE + 255) / 256, 256>>>(ei, nE);

    const int gemm_grid = (N_NODES + GT_ROWS - 1) / GT_ROWS;

    const __half* cur = pA;
    __half* nxt = pB;
    for (int l = 0; l < N_LAYERS; l++) {
        fused_layer_kernel<<<gemm_grid, 256, smem>>>(
            cur, nxt, bn, gamma, beta, out_node, l, (l == N_LAYERS - 1) ? 1 : 0);
        const __half* t = cur; cur = nxt; nxt = (__half*)t;
    }

    pool_kernel<<<POOL_B, 128>>>(out_node, batch, out_graph);
}

// round 11
// speedup vs baseline: 1.5863x; 1.5863x over previous
#include <cuda_runtime.h>
#include <cuda_fp16.h>
#include <cuda_bf16.h>

#define N_NODES   50000
#define N_EDGES   1600000
#define HID       128
#define KTOT      256            // combined K = [agg | x]
#define N_LAYERS  3
#define N_GRAPHS  64
#define LN_EPS    1e-5f
#define SCAN_B    ((N_NODES + 255) / 256)   // 196
#define POOL_B    ((N_NODES + 127) / 128)   // 391

// ---------------- static device scratch ---------------------------------------
__device__ __half g_xh  [(size_t)N_NODES * HID];    // fp16 layer input
__device__ __half g_aggh[(size_t)N_NODES * HID];    // fp16 mean-aggregated neighbors
__device__ __half g_wh  [(size_t)N_LAYERS * HID * KTOT]; // [l][n][k], transposed
__device__ int    g_deg_i[N_NODES];
__device__ int    g_cur  [N_NODES];
__device__ int    g_incl [N_NODES];
__device__ int    g_part [256];
__device__ int    g_csr  [N_EDGES];
__device__ int    g_scan_done;
__device__ int    g_pool_done;
__device__ float  g_gsum[N_GRAPHS * HID];
__device__ float  g_gcnt[N_GRAPHS];

// ---------------- fused init: zero + fp16 convert + weight transpose ----------
__global__ void init_kernel(const float* __restrict__ x,
                            const float* __restrict__ Wn,
                            const float* __restrict__ Wr) {
    int i = blockIdx.x * blockDim.x + threadIdx.x;     // 0 .. 1.6M-1
    if (i < N_NODES) { g_deg_i[i] = 0; g_cur[i] = 0; }
    if (i < N_GRAPHS * HID) g_gsum[i] = 0.0f;
    if (i < N_GRAPHS) g_gcnt[i] = 0.0f;
    if (i == 0) { g_scan_done = 0; g_pool_done = 0; }
    size_t e = (size_t)i * 4;
    if (e < (size_t)N_NODES * HID) {
        float4 v = *(const float4*)(x + e);
        __half2 h0 = __floats2half2_rn(v.x, v.y);
        __half2 h1 = __floats2half2_rn(v.z, v.w);
        uint2 packed;
        packed.x = *(unsigned*)&h0;
        packed.y = *(unsigned*)&h1;
        *(uint2*)(g_xh + e) = packed;
    }
    if (i < N_LAYERS * HID * KTOT) {
        int k = i & 255;
        int n = (i >> 8) & 127;
        int l = i >> 15;
        float v = (k < HID) ? __ldg(&Wn[((size_t)l * HID + k) * HID + n])
                            : __ldg(&Wr[((size_t)l * HID + (k - HID)) * HID + n]);
        g_wh[i] = __float2half_rn(v);
    }
}

// ---------------- CSR build (R8-proven: RED count + cursor fill) --------------
__global__ void count_kernel(const int* __restrict__ ei, int nE) {
    int e = blockIdx.x * blockDim.x + threadIdx.x;
    if (e >= nE) return;
    atomicAdd(&g_deg_i[__ldg(ei + nE + e)], 1);     // fire-and-forget -> RED
}

__global__ void scan12_kernel() {
    __shared__ int s[256];
    __shared__ int lastflag;
    int t = threadIdx.x;
    int i = blockIdx.x * 256 + t;
    int v = (i < N_NODES) ? g_deg_i[i] : 0;
    s[t] = v; __syncthreads();
    #pragma unroll
    for (int d = 1; d < 256; d <<= 1) {
        int u = (t >= d) ? s[t - d] : 0;
        __syncthreads();
        s[t] += u;
        __syncthreads();
    }
    if (i < N_NODES) g_incl[i] = s[t];
    if (t == 255) g_part[blockIdx.x] = s[255];
    __threadfence();
    if (t == 0) {
        int old = atomicAdd(&g_scan_done, 1);
        lastflag = (old == gridDim.x - 1);
    }
    __syncthreads();
    if (lastflag) {
        int pv = (t < SCAN_B) ? g_part[t] : 0;
        s[t] = pv; __syncthreads();
        #pragma unroll
        for (int d = 1; d < 256; d <<= 1) {
            int u = (t >= d) ? s[t - d] : 0;
            __syncthreads();
            s[t] += u;
            __syncthreads();
        }
        if (t < SCAN_B) g_part[t] = s[t] - pv;   // exclusive
    }
}

__global__ void fill_kernel(const int* __restrict__ ei, int nE) {
    int e = blockIdx.x * blockDim.x + threadIdx.x;
    if (e >= nE) return;
    int s = __ldg(ei + e);
    int d = __ldg(ei + nE + e);
    int base = __ldg(&g_part[d >> 8]) + __ldg(&g_incl[d]) - __ldg(&g_deg_i[d]);
    int pos = base + atomicAdd(&g_cur[d], 1);
    g_csr[pos] = s;
}

// ---------------- gather aggregation from fp16 table: warp per node -----------
__global__ __launch_bounds__(256) void gather_kernel()
{
    int w    = (blockIdx.x * blockDim.x + threadIdx.x) >> 5;
    int lane = threadIdx.x & 31;
    if (w >= N_NODES) return;
    int deg = __ldg(&g_deg_i[w]);
    int beg = __ldg(&g_part[w >> 8]) + __ldg(&g_incl[w]) - deg;

    float a0 = 0.f, a1 = 0.f, a2 = 0.f, a3 = 0.f;
    int j = 0;
    for (; j + 8 <= deg; j += 8) {
        int idx[8];
        #pragma unroll
        for (int u = 0; u < 8; u++) idx[u] = __ldg(&g_csr[beg + j + u]);
        uint2 v[8];
        #pragma unroll
        for (int u = 0; u < 8; u++)
            v[u] = __ldg((const uint2*)(g_xh + (size_t)idx[u] * HID) + lane);
        #pragma unroll
        for (int u = 0; u < 8; u++) {
            float2 f0 = __half22float2(*(__half2*)&v[u].x);
            float2 f1 = __half22float2(*(__half2*)&v[u].y);
            a0 += f0.x; a1 += f0.y; a2 += f1.x; a3 += f1.y;
        }
    }
    for (; j < deg; j++) {
        int s0 = __ldg(&g_csr[beg + j]);
        uint2 v0 = __ldg((const uint2*)(g_xh + (size_t)s0 * HID) + lane);
        float2 f0 = __half22float2(*(__half2*)&v0.x);
        float2 f1 = __half22float2(*(__half2*)&v0.y);
        a0 += f0.x; a1 += f0.y; a2 += f1.x; a3 += f1.y;
    }
    float id = 1.0f / fmaxf((float)deg, 1.0f);
    __half2 h0 = __floats2half2_rn(a0 * id, a1 * id);
    __half2 h1 = __floats2half2_rn(a2 * id, a3 * id);
    uint2 packed;
    packed.x = *(unsigned*)&h0;
    packed.y = *(unsigned*)&h1;
    ((uint2*)(g_aggh + (size_t)w * HID))[lane] = packed;
}

// ---------------- HMMA fused dual-GEMM + LN + ReLU ----------------------------
#define GT_ROWS 128

__device__ __forceinline__ unsigned ldsm_addr(const __half* base_sm, int row, int chunk) {
    return (unsigned)__cvta_generic_to_shared(base_sm) +
           (((row << 5) + (chunk ^ (row & 7))) << 4);
}

__global__ __launch_bounds__(256, 1) void hmma_ln_kernel(
    const float* __restrict__ bn, const float* __restrict__ gamma,
    const float* __restrict__ beta, float* __restrict__ out_fp32,
    int layer, int write_fp32)
{
    extern __shared__ __half smh[];
    __half* A_s = smh;                  // 128*256
    __half* W_s = smh + GT_ROWS * KTOT; // 128*256
    float*  red = (float*)smh;          // epilogue reuse

    const int tid  = threadIdx.x;
    const int lane = tid & 31;
    const int warp = tid >> 5;
    const int wm   = warp & 3;
    const int wn   = warp >> 2;
    const int m0   = wm * 32;
    const int n0   = wn * 64;
    const int row0 = blockIdx.x * GT_ROWS;

    for (int q = tid; q < GT_ROWS * 32; q += 256) {
        int r = q >> 5;
        int c = q & 31;
        int row = row0 + r;
        uint4 v = make_uint4(0, 0, 0, 0);
        if (row < N_NODES) {
            const __half* src = (c < 16) ? (g_aggh + (size_t)row * HID + c * 8)
                                         : (g_xh  + (size_t)row * HID + (c - 16) * 8);
            v = *(const uint4*)src;
        }
        *(uint4*)(A_s + (((r << 5) + (c ^ (r & 7))) << 3)) = v;
    }
    const __half* wl = g_wh + (size_t)layer * HID * KTOT;
    for (int q = tid; q < HID * 32; q += 256) {
        int n = q >> 5;
        int c = q & 31;
        uint4 v = *(const uint4*)(wl + (size_t)n * KTOT + c * 8);
        *(uint4*)(W_s + (((n << 5) + (c ^ (n & 7))) << 3)) = v;
    }
    __syncthreads();

    float acc[2][8][4];
    #pragma unroll
    for (int mt = 0; mt < 2; mt++)
        #pragma unroll
        for (int nt = 0; nt < 8; nt++)
            #pragma unroll
            for (int v = 0; v < 4; v++) acc[mt][nt][v] = 0.0f;

    const int a_row0 = m0 + (lane & 15);
    const int b_row0 = n0 + (lane & 15);
    const int hi     = lane >> 4;

    #pragma unroll 4
    for (int kk = 0; kk < KTOT / 16; kk++) {
        int cbase = kk * 2 + hi;
        unsigned a[2][4];
        #pragma unroll
        for (int mt = 0; mt < 2; mt++) {
            unsigned addr = ldsm_addr(A_s, a_row0 + mt * 16, cbase);
            asm volatile("ldmatrix.sync.aligned.m8n8.x4.shared.b16 {%0,%1,%2,%3}, [%4];"
                         : "=r"(a[mt][0]), "=r"(a[mt][1]), "=r"(a[mt][2]), "=r"(a[mt][3])
                         : "r"(addr));
        }
        unsigned b[8][2];
        #pragma unroll
        for (int g = 0; g < 4; g++) {
            unsigned r0, r1, r2, r3;
            unsigned addr = ldsm_addr(W_s, b_row0 + g * 16, cbase);
            asm volatile("ldmatrix.sync.aligned.m8n8.x4.shared.b16 {%0,%1,%2,%3}, [%4];"
                         : "=r"(r0), "=r"(r1), "=r"(r2), "=r"(r3) : "r"(addr));
            b[g * 2 + 0][0] = r0; b[g * 2 + 0][1] = r2;
            b[g * 2 + 1][0] = r1; b[g * 2 + 1][1] = r3;
        }
        #pragma unroll
        for (int mt = 0; mt < 2; mt++)
            #pragma unroll
            for (int nt = 0; nt < 8; nt++)
                asm volatile(
                    "mma.sync.aligned.m16n8k16.row.col.f32.f16.f16.f32 "
                    "{%0,%1,%2,%3}, {%4,%5,%6,%7}, {%8,%9}, {%0,%1,%2,%3};"
                    : "+f"(acc[mt][nt][0]), "+f"(acc[mt][nt][1]),
                      "+f"(acc[mt][nt][2]), "+f"(acc[mt][nt][3])
                    : "r"(a[mt][0]), "r"(a[mt][1]), "r"(a[mt][2]), "r"(a[mt][3]),
                      "r"(b[nt][0]), "r"(b[nt][1]));
    }

    const int gid  = lane >> 2;
    const int pair = lane & 3;

    float2 bv[8], gv[8], btv[8];
    #pragma unroll
    for (int nt = 0; nt < 8; nt++) {
        int col = n0 + nt * 8 + pair * 2;
        bv[nt]  = *(const float2*)(bn    + layer * HID + col);
        gv[nt]  = *(const float2*)(gamma + layer * HID + col);
        btv[nt] = *(const float2*)(beta  + layer * HID + col);
    }
    #pragma unroll
    for (int mt = 0; mt < 2; mt++)
        #pragma unroll
        for (int nt = 0; nt < 8; nt++) {
            acc[mt][nt][0] += bv[nt].x; acc[mt][nt][1] += bv[nt].y;
            acc[mt][nt][2] += bv[nt].x; acc[mt][nt][3] += bv[nt].y;
        }

    float s[4] = {0, 0, 0, 0}, qq[4] = {0, 0, 0, 0};
    #pragma unroll
    for (int mt = 0; mt < 2; mt++)
        #pragma unroll
        for (int nt = 0; nt < 8; nt++) {
            float c0 = acc[mt][nt][0], c1 = acc[mt][nt][1];
            float c2 = acc[mt][nt][2], c3 = acc[mt][nt][3];
            s [mt * 2 + 0] += c0 + c1;       qq[mt * 2 + 0] += c0 * c0 + c1 * c1;
            s [mt * 2 + 1] += c2 + c3;       qq[mt * 2 + 1] += c2 * c2 + c3 * c3;
        }
    #pragma unroll
    for (int v = 0; v < 4; v++) {
        s [v] += __shfl_xor_sync(0xffffffffu, s [v], 1);
        s [v] += __shfl_xor_sync(0xffffffffu, s [v], 2);
        qq[v] += __shfl_xor_sync(0xffffffffu, qq[v], 1);
        qq[v] += __shfl_xor_sync(0xffffffffu, qq[v], 2);
    }

    __syncthreads();
    if (pair == 0) {
        #pragma unroll
        for (int v = 0; v < 4; v++) {
            int rl = m0 + (v >> 1) * 16 + (v & 1) * 8 + gid;
            red[wn * 128 + rl]       = s[v];
            red[256 + wn * 128 + rl] = qq[v];
        }
    }
    __syncthreads();

    const float inv128 = 1.0f / 128.0f;
    #pragma unroll
    for (int v = 0; v < 4; v++) {
        int rl  = m0 + (v >> 1) * 16 + (v & 1) * 8 + gid;
        int row = row0 + rl;
        float ts = red[rl] + red[128 + rl];
        float tq = red[256 + rl] + red[384 + rl];
        float mu  = ts * inv128;
        float var = tq * inv128 - mu * mu;
        float rs  = rsqrtf(var + LN_EPS);
        if (row < N_NODES) {
            int mt = v >> 1;
            int lo = (v & 1) * 2;
            #pragma unroll
            for (int nt = 0; nt < 8; nt++) {
                float o0 = fmaxf((acc[mt][nt][lo + 0] - mu) * rs * gv[nt].x + btv[nt].x, 0.0f);
                float o1 = fmaxf((acc[mt][nt][lo + 1] - mu) * rs * gv[nt].y + btv[nt].y, 0.0f);
                int col = n0 + nt * 8 + pair * 2;
                if (write_fp32) {
                    *(float2*)(out_fp32 + (size_t)row * HID + col) = make_float2(o0, o1);
                } else {
                    __half2 h = __floats2half2_rn(o0, o1);
                    *(__half2*)(g_xh + (size_t)row * HID + col) = h;
                }
            }
        }
    }
}

// ---------------- graph pooling + finalize (fused via done-counter) -----------
__global__ __launch_bounds__(128) void pool_kernel(
    const float* __restrict__ node_emb, const int* __restrict__ batch,
    float* __restrict__ out_graph)
{
    __shared__ int sb[128];
    __shared__ int lastflag;
    int n0 = blockIdx.x * 128;
    int c  = threadIdx.x;
    int nmax = min(128, N_NODES - n0);
    if (c < nmax) sb[c] = batch[n0 + c];
    __syncthreads();

    float sum = 0.f;
    int curg = sb[0];
    int runlen = 0;
    for (int t = 0; t < nmax; t++) {
        int g = sb[t];
        if (g != curg) {
            atomicAdd(&g_gsum[curg * HID + c], sum);
            if (c == 0) atomicAdd(&g_gcnt[curg], (float)runlen);
            sum = 0.f; runlen = 0; curg = g;
        }
        sum += node_emb[(size_t)(n0 + t) * HID + c];
        runlen++;
    }
    atomicAdd(&g_gsum[curg * HID + c], sum);
    if (c == 0) atomicAdd(&g_gcnt[curg], (float)runlen);

    __threadfence();
    if (c == 0) {
        int old = atomicAdd(&g_pool_done, 1);
        lastflag = (old == gridDim.x - 1);
    }
    __syncthreads();
    if (lastflag) {
        for (int i = c; i < N_GRAPHS * HID; i += 128) {
            int g = i >> 7;
            float cnt = fmaxf(g_gcnt[g], 1.0f);
            out_graph[i] = g_gsum[i] / cnt;
        }
    }
}

extern "C" void kernel_launch(void* const* d_in, const int* in_sizes, int n_in,
                              void* d_out, int out_size)
{
    const float* x     = (const float*)d_in[0];
    const float* Wn    = (const float*)d_in[1];
    const float* bn    = (const float*)d_in[2];
    const float* Wr    = (const float*)d_in[3];
    const float* gamma = (const float*)d_in[4];
    const float* beta  = (const float*)d_in[5];
    const int*   ei    = (const int*)  d_in[6];
    const int*   batch = (const int*)  d_in[7];
    float* out = (float*)d_out;
    float* out_graph = out;                       // [64,128]
    float* out_node  = out + N_GRAPHS * HID;      // [50000,128]

    const int nE = in_sizes[6] / 2;

    static bool inited = false;
    if (!inited) {
        inited = true;
        cudaFuncSetAttribute(hmma_ln_kernel,
                             cudaFuncAttributeMaxDynamicSharedMemorySize,
                             2 * GT_ROWS * KTOT * (int)sizeof(__half));
    }
    const size_t smem = 2 * GT_ROWS * KTOT * sizeof(__half);   // 128 KB

    // fused init: zero + fp16 convert + weight transpose
    init_kernel<<<((N_NODES * HID / 4) + 255) / 256, 256>>>(x, Wn, Wr);
    // CSR build (R8-proven: RED count + cursor fill)
    count_kernel<<<(nE + 255) / 256, 256>>>(ei, nE);
    scan12_kernel<<<SCAN_B, 256>>>();
    fill_kernel<<<(nE + 255) / 256, 256>>>(ei, nE);

    const int gemm_grid   = (N_NODES + GT_ROWS - 1) / GT_ROWS;
    const int gather_grid = (N_NODES * 32 + 255) / 256;

    for (int l = 0; l < N_LAYERS; l++) {
        gather_kernel<<<gather_grid, 256>>>();
        hmma_ln_kernel<<<gemm_grid, 256, smem>>>(
            bn, gamma, beta, out_node, l, (l == N_LAYERS - 1) ? 1 : 0);
    }

    pool_kernel<<<POOL_B, 128>>>(out_node, batch, out_graph);
}

// round 12
// speedup vs baseline: 1.9014x; 1.1986x over previous
#include <cuda_runtime.h>
#include <cuda_fp16.h>
#include <cuda_bf16.h>

#define N_NODES   50000
#define N_EDGES   1600000
#define HID       128
#define KTOT      256            // combined K = [agg | x]
#define N_LAYERS  3
#define N_GRAPHS  64
#define LN_EPS    1e-5f
#define SCAN_B    ((N_NODES + 255) / 256)   // 196
#define POOL_B    ((N_NODES + 127) / 128)   // 391
#define GT_ROWS   128

// ---------------- static device scratch ---------------------------------------
__device__ __half g_xh  [(size_t)N_NODES * HID];    // fp16 layer input
__device__ __half g_aggh[(size_t)N_NODES * HID];    // fp16 mean-aggregated neighbors
__device__ __half g_wh  [(size_t)N_LAYERS * HID * KTOT]; // [l][n][k], transposed
__device__ int    g_deg_i[N_NODES];
__device__ int    g_cur  [N_NODES];
__device__ int    g_incl [N_NODES];
__device__ int    g_part [256];
__device__ int    g_csr  [N_EDGES];
__device__ int    g_scan_done;
__device__ float  g_gsum[N_GRAPHS * HID];
__device__ float  g_gcnt[N_GRAPHS];

// ---------------- fused init: zero + fp16 convert + weight transpose ----------
__global__ void init_kernel(const float* __restrict__ x,
                            const float* __restrict__ Wn,
                            const float* __restrict__ Wr) {
    int i = blockIdx.x * blockDim.x + threadIdx.x;     // 0 .. 1.6M-1
    if (i < N_NODES) { g_deg_i[i] = 0; g_cur[i] = 0; }
    if (i < N_GRAPHS * HID) g_gsum[i] = 0.0f;
    if (i < N_GRAPHS) g_gcnt[i] = 0.0f;
    if (i == 0) g_scan_done = 0;
    size_t e = (size_t)i * 4;
    if (e < (size_t)N_NODES * HID) {
        float4 v = *(const float4*)(x + e);
        __half2 h0 = __floats2half2_rn(v.x, v.y);
        __half2 h1 = __floats2half2_rn(v.z, v.w);
        uint2 packed;
        packed.x = *(unsigned*)&h0;
        packed.y = *(unsigned*)&h1;
        *(uint2*)(g_xh + e) = packed;
    }
    if (i < N_LAYERS * HID * KTOT) {
        int k = i & 255;
        int n = (i >> 8) & 127;
        int l = i >> 15;
        float v = (k < HID) ? __ldg(&Wn[((size_t)l * HID + k) * HID + n])
                            : __ldg(&Wr[((size_t)l * HID + (k - HID)) * HID + n]);
        g_wh[i] = __float2half_rn(v);
    }
}

// ---------------- CSR build (R8-proven: RED count + cursor fill) --------------
__global__ void count_kernel(const int* __restrict__ ei, int nE) {
    int e = blockIdx.x * blockDim.x + threadIdx.x;
    if (e >= nE) return;
    atomicAdd(&g_deg_i[__ldg(ei + nE + e)], 1);     // fire-and-forget -> RED
}

__global__ void scan12_kernel() {
    __shared__ int s[256];
    __shared__ int lastflag;
    int t = threadIdx.x;
    int i = blockIdx.x * 256 + t;
    int v = (i < N_NODES) ? g_deg_i[i] : 0;
    s[t] = v; __syncthreads();
    #pragma unroll
    for (int d = 1; d < 256; d <<= 1) {
        int u = (t >= d) ? s[t - d] : 0;
        __syncthreads();
        s[t] += u;
        __syncthreads();
    }
    if (i < N_NODES) g_incl[i] = s[t];
    if (t == 255) g_part[blockIdx.x] = s[255];
    __threadfence();
    if (t == 0) {
        int old = atomicAdd(&g_scan_done, 1);
        lastflag = (old == gridDim.x - 1);
    }
    __syncthreads();
    if (lastflag) {
        int pv = (t < SCAN_B) ? g_part[t] : 0;
        s[t] = pv; __syncthreads();
        #pragma unroll
        for (int d = 1; d < 256; d <<= 1) {
            int u = (t >= d) ? s[t - d] : 0;
            __syncthreads();
            s[t] += u;
            __syncthreads();
        }
        if (t < SCAN_B) g_part[t] = s[t] - pv;   // exclusive
    }
}

__global__ void fill_kernel(const int* __restrict__ ei, int nE) {
    int e = blockIdx.x * blockDim.x + threadIdx.x;
    if (e >= nE) return;
    int s = __ldg(ei + e);
    int d = __ldg(ei + nE + e);
    int base = __ldg(&g_part[d >> 8]) + __ldg(&g_incl[d]) - __ldg(&g_deg_i[d]);
    int pos = base + atomicAdd(&g_cur[d], 1);
    g_csr[pos] = s;
}

// ---------------- gather aggregation from fp16 table: warp per node -----------
__global__ __launch_bounds__(256) void gather_kernel()
{
    int w    = (blockIdx.x * blockDim.x + threadIdx.x) >> 5;
    int lane = threadIdx.x & 31;
    if (w >= N_NODES) return;
    int deg = __ldg(&g_deg_i[w]);
    int beg = __ldg(&g_part[w >> 8]) + __ldg(&g_incl[w]) - deg;

    float a0 = 0.f, a1 = 0.f, a2 = 0.f, a3 = 0.f;
    int j = 0;
    for (; j + 8 <= deg; j += 8) {
        int idx[8];
        #pragma unroll
        for (int u = 0; u < 8; u++) idx[u] = __ldg(&g_csr[beg + j + u]);
        uint2 v[8];
        #pragma unroll
        for (int u = 0; u < 8; u++)
            v[u] = __ldg((const uint2*)(g_xh + (size_t)idx[u] * HID) + lane);
        #pragma unroll
        for (int u = 0; u < 8; u++) {
            float2 f0 = __half22float2(*(__half2*)&v[u].x);
            float2 f1 = __half22float2(*(__half2*)&v[u].y);
            a0 += f0.x; a1 += f0.y; a2 += f1.x; a3 += f1.y;
        }
    }
    for (; j < deg; j++) {
        int s0 = __ldg(&g_csr[beg + j]);
        uint2 v0 = __ldg((const uint2*)(g_xh + (size_t)s0 * HID) + lane);
        float2 f0 = __half22float2(*(__half2*)&v0.x);
        float2 f1 = __half22float2(*(__half2*)&v0.y);
        a0 += f0.x; a1 += f0.y; a2 += f1.x; a3 += f1.y;
    }
    float id = 1.0f / fmaxf((float)deg, 1.0f);
    __half2 h0 = __floats2half2_rn(a0 * id, a1 * id);
    __half2 h1 = __floats2half2_rn(a2 * id, a3 * id);
    uint2 packed;
    packed.x = *(unsigned*)&h0;
    packed.y = *(unsigned*)&h1;
    ((uint2*)(g_aggh + (size_t)w * HID))[lane] = packed;
}

// ---------------- HMMA fused dual-GEMM + LN + ReLU ----------------------------
// K split into two 128-wide passes over 64 KB smem (A_s 32K + W_s 32K) so
// 3 blocks/SM co-reside; accumulators carry across passes.
// pass 0: aggh @ Wn-half, pass 1: xh @ Wr-half.
#define KCH 128          // K per pass
#define NCHUNK 16        // 16B chunks per row (128 halves)

__device__ __forceinline__ unsigned ldsm_addr16(const __half* base_sm, int row, int chunk) {
    return (unsigned)__cvta_generic_to_shared(base_sm) +
           (((row << 4) + (chunk ^ (row & 7))) << 4);
}

__global__ __launch_bounds__(256, 2) void hmma_ln_kernel(
    const float* __restrict__ bn, const float* __restrict__ gamma,
    const float* __restrict__ beta, float* __restrict__ out_fp32,
    int layer, int write_fp32)
{
    extern __shared__ __half smh[];
    __half* A_s = smh;                   // 128 x 128 swizzled (32 KB)
    __half* W_s = smh + GT_ROWS * KCH;   // 128 x 128 swizzled (32 KB)
    float*  red = (float*)smh;           // epilogue reuse (2 KB)

    const int tid  = threadIdx.x;
    const int lane = tid & 31;
    const int warp = tid >> 5;
    const int wm   = warp & 3;
    const int wn   = warp >> 2;
    const int m0   = wm * 32;
    const int n0   = wn * 64;
    const int row0 = blockIdx.x * GT_ROWS;

    float acc[2][8][4];
    #pragma unroll
    for (int mt = 0; mt < 2; mt++)
        #pragma unroll
        for (int nt = 0; nt < 8; nt++)
            #pragma unroll
            for (int v = 0; v < 4; v++) acc[mt][nt][v] = 0.0f;

    const int a_row0 = m0 + (lane & 15);
    const int b_row0 = n0 + (lane & 15);
    const int hi     = lane >> 4;
    const __half* wl = g_wh + (size_t)layer * HID * KTOT;

    #pragma unroll
    for (int pass = 0; pass < 2; pass++) {
        const __half* asrc = (pass == 0) ? g_aggh : g_xh;
        // stage A: 128 rows x 16 chunks
        for (int q = tid; q < GT_ROWS * NCHUNK; q += 256) {
            int r = q & 127;
            int c = q >> 7;
            int row = row0 + r;
            uint4 v = make_uint4(0, 0, 0, 0);
            if (row < N_NODES)
                v = *(const uint4*)(asrc + (size_t)row * HID + c * 8);
            *(uint4*)(A_s + (((r << 4) + (c ^ (r & 7))) << 3)) = v;
        }
        // stage W half: 128 n-rows x 16 chunks from wl[n][pass*128 + ...]
        for (int q = tid; q < HID * NCHUNK; q += 256) {
            int n = q & 127;
            int c = q >> 7;
            uint4 v = *(const uint4*)(wl + (size_t)n * KTOT + pass * KCH + c * 8);
            *(uint4*)(W_s + (((n << 4) + (c ^ (n & 7))) << 3)) = v;
        }
        __syncthreads();

        #pragma unroll
        for (int kk = 0; kk < KCH / 16; kk++) {
            int cbase = kk * 2 + hi;
            unsigned a[2][4];
            #pragma unroll
            for (int mt = 0; mt < 2; mt++) {
                unsigned addr = ldsm_addr16(A_s, a_row0 + mt * 16, cbase);
                asm volatile("ldmatrix.sync.aligned.m8n8.x4.shared.b16 {%0,%1,%2,%3}, [%4];"
                             : "=r"(a[mt][0]), "=r"(a[mt][1]), "=r"(a[mt][2]), "=r"(a[mt][3])
                             : "r"(addr));
            }
            unsigned b[8][2];
            #pragma unroll
            for (int g = 0; g < 4; g++) {
                unsigned r0, r1, r2, r3;
                unsigned addr = ldsm_addr16(W_s, b_row0 + g * 16, cbase);
                asm volatile("ldmatrix.sync.aligned.m8n8.x4.shared.b16 {%0,%1,%2,%3}, [%4];"
                             : "=r"(r0), "=r"(r1), "=r"(r2), "=r"(r3) : "r"(addr));
                b[g * 2 + 0][0] = r0; b[g * 2 + 0][1] = r2;
                b[g * 2 + 1][0] = r1; b[g * 2 + 1][1] = r3;
            }
            #pragma unroll
            for (int mt = 0; mt < 2; mt++)
                #pragma unroll
                for (int nt = 0; nt < 8; nt++)
                    asm volatile(
                        "mma.sync.aligned.m16n8k16.row.col.f32.f16.f16.f32 "
                        "{%0,%1,%2,%3}, {%4,%5,%6,%7}, {%8,%9}, {%0,%1,%2,%3};"
                        : "+f"(acc[mt][nt][0]), "+f"(acc[mt][nt][1]),
                          "+f"(acc[mt][nt][2]), "+f"(acc[mt][nt][3])
                        : "r"(a[mt][0]), "r"(a[mt][1]), "r"(a[mt][2]), "r"(a[mt][3]),
                          "r"(b[nt][0]), "r"(b[nt][1]));
        }
        __syncthreads();   // safe to overwrite buffers next pass / reuse as red
    }

    // ---- epilogue: bias, LN stats, affine, relu (identical to R8) ----
    const int gid  = lane >> 2;
    const int pair = lane & 3;

    float2 bv[8], gv[8], btv[8];
    #pragma unroll
    for (int nt = 0; nt < 8; nt++) {
        int col = n0 + nt * 8 + pair * 2;
        bv[nt]  = *(const float2*)(bn    + layer * HID + col);
        gv[nt]  = *(const float2*)(gamma + layer * HID + col);
        btv[nt] = *(const float2*)(beta  + layer * HID + col);
    }
    #pragma unroll
    for (int mt = 0; mt < 2; mt++)
        #pragma unroll
        for (int nt = 0; nt < 8; nt++) {
            acc[mt][nt][0] += bv[nt].x; acc[mt][nt][1] += bv[nt].y;
            acc[mt][nt][2] += bv[nt].x; acc[mt][nt][3] += bv[nt].y;
        }

    float s[4] = {0, 0, 0, 0}, qq[4] = {0, 0, 0, 0};
    #pragma unroll
    for (int mt = 0; mt < 2; mt++)
        #pragma unroll
        for (int nt = 0; nt < 8; nt++) {
            float c0 = acc[mt][nt][0], c1 = acc[mt][nt][1];
            float c2 = acc[mt][nt][2], c3 = acc[mt][nt][3];
            s [mt * 2 + 0] += c0 + c1;       qq[mt * 2 + 0] += c0 * c0 + c1 * c1;
            s [mt * 2 + 1] += c2 + c3;       qq[mt * 2 + 1] += c2 * c2 + c3 * c3;
        }
    #pragma unroll
    for (int v = 0; v < 4; v++) {
        s [v] += __shfl_xor_sync(0xffffffffu, s [v], 1);
        s [v] += __shfl_xor_sync(0xffffffffu, s [v], 2);
        qq[v] += __shfl_xor_sync(0xffffffffu, qq[v], 1);
        qq[v] += __shfl_xor_sync(0xffffffffu, qq[v], 2);
    }

    if (pair == 0) {
        #pragma unroll
        for (int v = 0; v < 4; v++) {
            int rl = m0 + (v >> 1) * 16 + (v & 1) * 8 + gid;
            red[wn * 128 + rl]       = s[v];
            red[256 + wn * 128 + rl] = qq[v];
        }
    }
    __syncthreads();

    const float inv128 = 1.0f / 128.0f;
    #pragma unroll
    for (int v = 0; v < 4; v++) {
        int rl  = m0 + (v >> 1) * 16 + (v & 1) * 8 + gid;
        int row = row0 + rl;
        float ts = red[rl] + red[128 + rl];
        float tq = red[256 + rl] + red[384 + rl];
        float mu  = ts * inv128;
        float var = tq * inv128 - mu * mu;
        float rs  = rsqrtf(var + LN_EPS);
        if (row < N_NODES) {
            int mt = v >> 1;
            int lo = (v & 1) * 2;
            #pragma unroll
            for (int nt = 0; nt < 8; nt++) {
                float o0 = fmaxf((acc[mt][nt][lo + 0] - mu) * rs * gv[nt].x + btv[nt].x, 0.0f);
                float o1 = fmaxf((acc[mt][nt][lo + 1] - mu) * rs * gv[nt].y + btv[nt].y, 0.0f);
                int col = n0 + nt * 8 + pair * 2;
                if (write_fp32) {
                    *(float2*)(out_fp32 + (size_t)row * HID + col) = make_float2(o0, o1);
                } else {
                    __half2 h = __floats2half2_rn(o0, o1);
                    *(__half2*)(g_xh + (size_t)row * HID + col) = h;
                }
            }
        }
    }
}

// ---------------- graph pooling (R8 form: separate finalize) ------------------
__global__ __launch_bounds__(128) void pool_kernel(
    const float* __restrict__ node_emb, const int* __restrict__ batch)
{
    __shared__ int sb[128];
    int n0 = blockIdx.x * 128;
    int c  = threadIdx.x;
    int nmax = min(128, N_NODES - n0);
    if (c < nmax) sb[c] = batch[n0 + c];
    __syncthreads();

    float sum = 0.f;
    int curg = sb[0];
    int runlen = 0;
    for (int t = 0; t < nmax; t++) {
        int g = sb[t];
        if (g != curg) {
            atomicAdd(&g_gsum[curg * HID + c], sum);
            if (c == 0) atomicAdd(&g_gcnt[curg], (float)runlen);
            sum = 0.f; runlen = 0; curg = g;
        }
        sum += node_emb[(size_t)(n0 + t) * HID + c];
        runlen++;
    }
    atomicAdd(&g_gsum[curg * HID + c], sum);
    if (c == 0) atomicAdd(&g_gcnt[curg], (float)runlen);
}

__global__ void finalize_kernel(float* __restrict__ out_graph) {
    int g = blockIdx.x;
    int c = threadIdx.x;
    float cnt = fmaxf(g_gcnt[g], 1.0f);
    out_graph[g * HID + c] = g_gsum[g * HID + c] / cnt;
}

extern "C" void kernel_launch(void* const* d_in, const int* in_sizes, int n_in,
                              void* d_out, int out_size)
{
    const float* x     = (const float*)d_in[0];
    const float* Wn    = (const float*)d_in[1];
    const float* bn    = (const float*)d_in[2];
    const float* Wr    = (const float*)d_in[3];
    const float* gamma = (const float*)d_in[4];
    const float* beta  = (const float*)d_in[5];
    const int*   ei    = (const int*)  d_in[6];
    const int*   batch = (const int*)  d_in[7];
    float* out = (float*)d_out;
    float* out_graph = out;                       // [64,128]
    float* out_node  = out + N_GRAPHS * HID;      // [50000,128]

    const int nE = in_sizes[6] / 2;

    static bool inited = false;
    if (!inited) {
        inited = true;
        cudaFuncSetAttribute(hmma_ln_kernel,
                             cudaFuncAttributeMaxDynamicSharedMemorySize,
                             2 * GT_ROWS * KCH * (int)sizeof(__half));
    }
    const size_t smem = 2 * GT_ROWS * KCH * sizeof(__half);   // 64 KB

    // fused init: zero + fp16 convert + weight transpose
    init_kernel<<<((N_NODES * HID / 4) + 255) / 256, 256>>>(x, Wn, Wr);
    // CSR build (R8-proven: RED count + cursor fill)
    count_kernel<<<(nE + 255) / 256, 256>>>(ei, nE);
    scan12_kernel<<<SCAN_B, 256>>>();
    fill_kernel<<<(nE + 255) / 256, 256>>>(ei, nE);

    const int gemm_grid   = (N_NODES + GT_ROWS - 1) / GT_ROWS;
    const int gather_grid = (N_NODES * 32 + 255) / 256;

    for (int l = 0; l < N_LAYERS; l++) {
        gather_kernel<<<gather_grid, 256>>>();
        hmma_ln_kernel<<<gemm_grid, 256, smem>>>(
            bn, gamma, beta, out_node, l, (l == N_LAYERS - 1) ? 1 : 0);
    }

    pool_kernel<<<POOL_B, 128>>>(out_node, batch);
    finalize_kernel<<<N_GRAPHS, HID>>>(out_graph);
}